// round 2
// baseline (speedup 1.0000x reference)
#include <cuda_runtime.h>
#include <cstdint>

// GraphAttnMultiHead: N=8192 nodes, IN_F=256, H=4 heads, OUT_F=64 (H*OUT_F=256)
//
// Math restructure vs reference:
//   support[n, h*64+o] = (X @ W)[n, h*64+o]
//   f1[h,n] = <support[n, h-block], wu[h]>,  f2 likewise with wv
//   score(h,i,j) = lrelu(f1[h,j] + f2[h,i]) on edges (adj binary)
//   softmax shift m_hat[h,i] = lrelu(gmax_f1[h] + f2[h,i])  (valid upper bound,
//     ratio-invariant, no underflow since f1 spread is small)
//   out[i, h*64+o] = (sum_j p * support[j]) / (sum_j p)  + bias + X@projW^T + proj_b
//
// Kernels: prep Bcat -> fused GEMM (support | residual base) -> f1/f2 ->
//          per-head global max -> sparse PV (warp-per-row, ballot edge iter).

#define NN 8192
#define NEG 0.2f

__device__ float g_support[NN * 256];   // 8 MB
__device__ float g_bcat[256 * 512];     // [k][c] : c<256 -> W, c>=256 -> projW^T
__device__ float g_f1[4 * NN];
__device__ float g_f2[4 * NN];
__device__ float g_gmax[4];

// ---------------------------------------------------------------- prep Bcat
__global__ void prep_bcat_kernel(const float* __restrict__ weight,
                                 const float* __restrict__ projw) {
    int idx = blockIdx.x * blockDim.x + threadIdx.x;  // 512*256 = 131072
    int k = idx >> 9;
    int c = idx & 511;
    float v = (c < 256) ? weight[k * 256 + c] : projw[(c - 256) * 256 + k];
    g_bcat[k * 512 + c] = v;
}

// ------------------------------------------------- GEMM 8192 x 512 x 256 fp32
// C[:, 0:256] -> g_support ; C[:, 256:512] -> out (+ bias + proj_b)
__global__ __launch_bounds__(256) void gemm_kernel(
    const float* __restrict__ X, const float* __restrict__ bias,
    const float* __restrict__ projb, float* __restrict__ out) {
    __shared__ __align__(16) float As[16][132];  // [k][m], padded rows (528B = 33*16)
    __shared__ __align__(16) float Bs[16][68];   // [k][n], padded rows (272B = 17*16)

    int tid = threadIdx.x;
    int tx = tid & 15, ty = tid >> 4;
    int m0 = blockIdx.y * 128, n0 = blockIdx.x * 64;

    float acc[8][4];
#pragma unroll
    for (int ii = 0; ii < 8; ii++)
#pragma unroll
        for (int jj = 0; jj < 4; jj++) acc[ii][jj] = 0.f;

    int ar = tid >> 2, af = tid & 3;  // A loader: row base, k-float4 slot
    int bk = tid >> 4, bn = (tid & 15) * 4;

    for (int k0 = 0; k0 < 256; k0 += 16) {
#pragma unroll
        for (int r2 = 0; r2 < 2; r2++) {
            int row = ar + r2 * 64;
            float4 va = *(const float4*)(X + (size_t)(m0 + row) * 256 + k0 + af * 4);
            As[af * 4 + 0][row] = va.x;
            As[af * 4 + 1][row] = va.y;
            As[af * 4 + 2][row] = va.z;
            As[af * 4 + 3][row] = va.w;
        }
        float4 vb = *(const float4*)(g_bcat + (size_t)(k0 + bk) * 512 + n0 + bn);
        *(float4*)&Bs[bk][bn] = vb;
        __syncthreads();

#pragma unroll
        for (int k = 0; k < 16; k++) {
            float a[8], b[4];
            *(float4*)&a[0] = *(float4*)&As[k][ty * 8];
            *(float4*)&a[4] = *(float4*)&As[k][ty * 8 + 4];
            *(float4*)&b[0] = *(float4*)&Bs[k][tx * 4];
#pragma unroll
            for (int ii = 0; ii < 8; ii++)
#pragma unroll
                for (int jj = 0; jj < 4; jj++) acc[ii][jj] += a[ii] * b[jj];
        }
        __syncthreads();
    }

    if (n0 < 256) {
#pragma unroll
        for (int ii = 0; ii < 8; ii++) {
            int gm = m0 + ty * 8 + ii;
            *(float4*)(g_support + (size_t)gm * 256 + n0 + tx * 4) = *(float4*)&acc[ii][0];
        }
    } else {
        int c2 = n0 - 256 + tx * 4;
        float4 bb = *(const float4*)(bias + c2);
        float4 pb = *(const float4*)(projb + c2);
#pragma unroll
        for (int ii = 0; ii < 8; ii++) {
            int gm = m0 + ty * 8 + ii;
            float4 v;
            v.x = acc[ii][0] + bb.x + pb.x;
            v.y = acc[ii][1] + bb.y + pb.y;
            v.z = acc[ii][2] + bb.z + pb.z;
            v.w = acc[ii][3] + bb.w + pb.w;
            *(float4*)(out + (size_t)gm * 256 + c2) = v;
        }
    }
}

// -------------------------------------------------------------------- f1/f2
__global__ void f1f2_kernel(const float* __restrict__ wu,
                            const float* __restrict__ wv) {
    int gid = blockIdx.x * blockDim.x + threadIdx.x;  // 32768 = 8192*4
    int n = gid >> 2;
    int h = gid & 3;
    const float* sp = g_support + (size_t)n * 256 + h * 64;
    const float* u = wu + h * 64;
    const float* v = wv + h * 64;
    float s1 = 0.f, s2 = 0.f;
#pragma unroll 8
    for (int o = 0; o < 64; o++) {
        float s = sp[o];
        s1 += s * __ldg(u + o);
        s2 += s * __ldg(v + o);
    }
    g_f1[h * NN + n] = s1;
    g_f2[h * NN + n] = s2;
}

// ------------------------------------------------------- per-head global max
__global__ void gmax_kernel() {
    int h = blockIdx.x;
    __shared__ float sm[256];
    float local = -1e30f;
    for (int n = threadIdx.x; n < NN; n += 256)
        local = fmaxf(local, g_f1[h * NN + n]);
    sm[threadIdx.x] = local;
    __syncthreads();
    for (int s = 128; s > 0; s >>= 1) {
        if (threadIdx.x < s) sm[threadIdx.x] = fmaxf(sm[threadIdx.x], sm[threadIdx.x + s]);
        __syncthreads();
    }
    if (threadIdx.x == 0) g_gmax[h] = sm[0];
}

// ------------------------------------------------- sparse PV (warp-per-row)
// Warp handles row i, lane covers channels [lane*8, lane*8+8) (head = lane>>3).
// Ballot extracts edges from the adj row; per edge: coalesced 1KB gather of
// support[j], weighted by p = exp(lrelu(f1[j]+f2[i]) - m_hat). Denominator
// accumulated in-register per lane; normalize + residual-add at the end.
__global__ __launch_bounds__(256) void pv_kernel(const float* __restrict__ adj,
                                                 float* __restrict__ out) {
    int warp = (blockIdx.x * 256 + threadIdx.x) >> 5;
    int lane = threadIdx.x & 31;
    int i = warp;  // grid is exactly 8192 warps
    int h = lane >> 3;

    float f2i = g_f2[h * NN + i];
    float t = g_gmax[h] + f2i;
    float mhat = t > 0.f ? t : NEG * t;

    const float* __restrict__ arow = adj + (size_t)i * NN;
    const float* __restrict__ f1h = g_f1 + h * NN;
    const float* __restrict__ supb = g_support + lane * 8;

    float a0 = 0.f, a1 = 0.f, a2 = 0.f, a3 = 0.f;
    float a4 = 0.f, a5 = 0.f, a6 = 0.f, a7 = 0.f;
    float denom = 0.f;

    for (int j0 = 0; j0 < NN; j0 += 128) {
        float4 v = *(const float4*)(arow + j0 + lane * 4);
        unsigned m[4];
        m[0] = __ballot_sync(0xffffffffu, v.x != 0.f);
        m[1] = __ballot_sync(0xffffffffu, v.y != 0.f);
        m[2] = __ballot_sync(0xffffffffu, v.z != 0.f);
        m[3] = __ballot_sync(0xffffffffu, v.w != 0.f);
#pragma unroll
        for (int e = 0; e < 4; e++) {
            unsigned mm = m[e];  // warp-uniform: all lanes walk the same edges
            while (mm) {
                int src = __ffs(mm) - 1;
                mm &= mm - 1;
                int j = j0 + src * 4 + e;
                float s = __ldg(f1h + j) + f2i;
                s = s > 0.f ? s : NEG * s;
                float p = __expf(s - mhat);
                denom += p;
                const float4* sp = (const float4*)(supb + (size_t)j * 256);
                float4 x0 = __ldg(sp);
                float4 x1 = __ldg(sp + 1);
                a0 += p * x0.x; a1 += p * x0.y; a2 += p * x0.z; a3 += p * x0.w;
                a4 += p * x1.x; a5 += p * x1.y; a6 += p * x1.z; a7 += p * x1.w;
            }
        }
    }

    float inv = 1.f / denom;  // every row has a self-loop -> denom > 0
    float* op = out + (size_t)i * 256 + lane * 8;
    float4 o0 = *(float4*)op;
    float4 o1 = *((float4*)op + 1);
    o0.x += a0 * inv; o0.y += a1 * inv; o0.z += a2 * inv; o0.w += a3 * inv;
    o1.x += a4 * inv; o1.y += a5 * inv; o1.z += a6 * inv; o1.w += a7 * inv;
    *(float4*)op = o0;
    *((float4*)op + 1) = o1;
}

// ------------------------------------------------------------------- launch
extern "C" void kernel_launch(void* const* d_in, const int* in_sizes, int n_in,
                              void* d_out, int out_size) {
    const float* inputs = (const float*)d_in[0];   // [8192, 256]
    const float* adj    = (const float*)d_in[1];   // [8192, 8192]
    const float* weight = (const float*)d_in[2];   // [256, 256]
    const float* wu     = (const float*)d_in[3];   // [4, 64, 1]
    const float* wv     = (const float*)d_in[4];   // [4, 64, 1]
    const float* bias   = (const float*)d_in[5];   // [1, 256]
    const float* projw  = (const float*)d_in[6];   // [256, 256]
    const float* projb  = (const float*)d_in[7];   // [256]
    float* out = (float*)d_out;                    // [8192, 256]

    prep_bcat_kernel<<<512, 256>>>(weight, projw);
    gemm_kernel<<<dim3(8, 64), 256>>>(inputs, bias, projb, out);
    f1f2_kernel<<<128, 256>>>(wu, wv);
    gmax_kernel<<<4, 256>>>();
    pv_kernel<<<1024, 256>>>(adj, out);
}

// round 3
// speedup vs baseline: 1.1406x; 1.1406x over previous
#include <cuda_runtime.h>
#include <cuda_bf16.h>
#include <cstdint>

// GraphAttnMultiHead: N=8192, IN_F=256, H=4, OUT_F=64 (H*OUT_F=256)
//
// Restructure:
//   f1[h,n] = X[n] @ u2[h]   where u2[h,k] = sum_o W[k,h*64+o]*wu[h,o]   (exact assoc. swap)
//   f2 likewise with wv. Computed straight from X -> independent of GEMM.
//   support stored ONLY as bf16 (PV gather traffic + GEMM stores halved);
//   fp32 accumulation everywhere.
//   softmax shift m_hat[h,i] = lrelu(gmax_f1[h] + f2[h,i]) (ratio-invariant upper bound).
//   out = (sum_j p*support[j])/(sum_j p) + bias + X@projW^T + proj_b
//
// Launch order: prep -> f1f2(+atomic gmax) -> gemm -> pv

#define NN 8192
#define NEG 0.2f

__device__ __nv_bfloat16 g_supb[NN * 256];   // 4 MB bf16 support
__device__ float g_bcat[256 * 512];          // [k][c]: c<256 -> W, c>=256 -> projW^T
__device__ float g_u2[4 * 256];              // [h][k]
__device__ float g_v2[4 * 256];
__device__ float g_f1[4 * NN];
__device__ float g_f2[4 * NN];
__device__ unsigned g_gmax_enc[4];

// monotone float<->uint order encoding
__device__ __forceinline__ unsigned enc_f(float f) {
    unsigned b = __float_as_uint(f);
    return (b & 0x80000000u) ? ~b : (b | 0x80000000u);
}
__device__ __forceinline__ float dec_f(unsigned e) {
    unsigned b = (e & 0x80000000u) ? (e ^ 0x80000000u) : ~e;
    return __uint_as_float(b);
}

// ------------------------------------------------------------------- prep
// Builds bcat, u2/v2, and inits gmax encodings.
__global__ void prep_kernel(const float* __restrict__ weight,
                            const float* __restrict__ projw,
                            const float* __restrict__ wu,
                            const float* __restrict__ wv) {
    int idx = blockIdx.x * blockDim.x + threadIdx.x;  // 131072
    int k = idx >> 9;
    int c = idx & 511;
    float v = (c < 256) ? weight[k * 256 + c] : projw[(c - 256) * 256 + k];
    g_bcat[k * 512 + c] = v;

    if (idx < 2048) {  // h(4) x k(256) x {u,v}(2)
        int which = idx & 1;
        int kk = (idx >> 1) & 255;
        int h = idx >> 9;
        const float* wrow = weight + kk * 256 + h * 64;
        const float* uv = (which ? wv : wu) + h * 64;
        float s = 0.f;
#pragma unroll 8
        for (int o = 0; o < 64; o++) s += wrow[o] * __ldg(uv + o);
        (which ? g_v2 : g_u2)[h * 256 + kk] = s;
    }
    if (idx < 4) g_gmax_enc[idx] = 0u;
}

// ------------------------------------------------- f1/f2 + fused global max
// Thread per (n,h). Warp-reduce per-h max (lanes stride-4), 4 atomics/warp.
__global__ void f1f2_kernel(const float* __restrict__ X) {
    int gid = blockIdx.x * blockDim.x + threadIdx.x;  // 32768
    int n = gid >> 2;
    int h = gid & 3;
    const float* xr = X + (size_t)n * 256;
    const float* u = g_u2 + h * 256;
    const float* v = g_v2 + h * 256;
    float s1 = 0.f, s2 = 0.f;
#pragma unroll 8
    for (int k = 0; k < 256; k++) {
        float x = __ldg(xr + k);
        s1 += x * u[k];
        s2 += x * v[k];
    }
    g_f1[h * NN + n] = s1;
    g_f2[h * NN + n] = s2;

    // per-h warp max (lanes with same h are stride-4 apart)
    float m = s1;
    m = fmaxf(m, __shfl_xor_sync(0xffffffffu, m, 4));
    m = fmaxf(m, __shfl_xor_sync(0xffffffffu, m, 8));
    m = fmaxf(m, __shfl_xor_sync(0xffffffffu, m, 16));
    if ((threadIdx.x & 31) < 4) atomicMax(&g_gmax_enc[h], enc_f(m));
}

// ------------------------------------------------- GEMM 8192 x 512 x 256 fp32
// C[:, 0:256] -> g_supb (bf16) ; C[:, 256:512] -> out fp32 (+ bias + proj_b)
__global__ __launch_bounds__(256) void gemm_kernel(
    const float* __restrict__ X, const float* __restrict__ bias,
    const float* __restrict__ projb, float* __restrict__ out) {
    __shared__ __align__(16) float As[16][132];
    __shared__ __align__(16) float Bs[16][68];

    int tid = threadIdx.x;
    int tx = tid & 15, ty = tid >> 4;
    int m0 = blockIdx.y * 128, n0 = blockIdx.x * 64;

    float acc[8][4];
#pragma unroll
    for (int ii = 0; ii < 8; ii++)
#pragma unroll
        for (int jj = 0; jj < 4; jj++) acc[ii][jj] = 0.f;

    int ar = tid >> 2, af = tid & 3;
    int bk = tid >> 4, bn = (tid & 15) * 4;

    for (int k0 = 0; k0 < 256; k0 += 16) {
#pragma unroll
        for (int r2 = 0; r2 < 2; r2++) {
            int row = ar + r2 * 64;
            float4 va = *(const float4*)(X + (size_t)(m0 + row) * 256 + k0 + af * 4);
            As[af * 4 + 0][row] = va.x;
            As[af * 4 + 1][row] = va.y;
            As[af * 4 + 2][row] = va.z;
            As[af * 4 + 3][row] = va.w;
        }
        float4 vb = *(const float4*)(g_bcat + (size_t)(k0 + bk) * 512 + n0 + bn);
        *(float4*)&Bs[bk][bn] = vb;
        __syncthreads();

#pragma unroll
        for (int k = 0; k < 16; k++) {
            float a[8], b[4];
            *(float4*)&a[0] = *(float4*)&As[k][ty * 8];
            *(float4*)&a[4] = *(float4*)&As[k][ty * 8 + 4];
            *(float4*)&b[0] = *(float4*)&Bs[k][tx * 4];
#pragma unroll
            for (int ii = 0; ii < 8; ii++)
#pragma unroll
                for (int jj = 0; jj < 4; jj++) acc[ii][jj] += a[ii] * b[jj];
        }
        __syncthreads();
    }

    if (n0 < 256) {
#pragma unroll
        for (int ii = 0; ii < 8; ii++) {
            int gm = m0 + ty * 8 + ii;
            __nv_bfloat162 b0 = __float22bfloat162_rn(make_float2(acc[ii][0], acc[ii][1]));
            __nv_bfloat162 b1 = __float22bfloat162_rn(make_float2(acc[ii][2], acc[ii][3]));
            uint2 st;
            st.x = *(unsigned*)&b0;
            st.y = *(unsigned*)&b1;
            *(uint2*)(g_supb + (size_t)gm * 256 + n0 + tx * 4) = st;
        }
    } else {
        int c2 = n0 - 256 + tx * 4;
        float4 bb = *(const float4*)(bias + c2);
        float4 pb = *(const float4*)(projb + c2);
#pragma unroll
        for (int ii = 0; ii < 8; ii++) {
            int gm = m0 + ty * 8 + ii;
            float4 v;
            v.x = acc[ii][0] + bb.x + pb.x;
            v.y = acc[ii][1] + bb.y + pb.y;
            v.z = acc[ii][2] + bb.z + pb.z;
            v.w = acc[ii][3] + bb.w + pb.w;
            *(float4*)(out + (size_t)gm * 256 + c2) = v;
        }
    }
}

// ------------------------------------------------- sparse PV (warp-per-row)
// Warp = row i; lane covers 8 channels (head = lane>>3). Ballot edge
// extraction; per edge one 16B bf16 gather per lane (512B/warp vs 1KB fp32).
__global__ __launch_bounds__(256) void pv_kernel(const float* __restrict__ adj,
                                                 float* __restrict__ out) {
    int warp = (blockIdx.x * 256 + threadIdx.x) >> 5;
    int lane = threadIdx.x & 31;
    int i = warp;
    int h = lane >> 3;

    float f2i = g_f2[h * NN + i];
    float t = dec_f(g_gmax_enc[h]) + f2i;
    float mhat = t > 0.f ? t : NEG * t;

    const float* __restrict__ arow = adj + (size_t)i * NN;
    const float* __restrict__ f1h = g_f1 + h * NN;
    const __nv_bfloat16* __restrict__ supb = g_supb + lane * 8;

    float a0 = 0.f, a1 = 0.f, a2 = 0.f, a3 = 0.f;
    float a4 = 0.f, a5 = 0.f, a6 = 0.f, a7 = 0.f;
    float denom = 0.f;

    for (int j0 = 0; j0 < NN; j0 += 128) {
        float4 v = *(const float4*)(arow + j0 + lane * 4);
        unsigned m[4];
        m[0] = __ballot_sync(0xffffffffu, v.x != 0.f);
        m[1] = __ballot_sync(0xffffffffu, v.y != 0.f);
        m[2] = __ballot_sync(0xffffffffu, v.z != 0.f);
        m[3] = __ballot_sync(0xffffffffu, v.w != 0.f);
#pragma unroll
        for (int e = 0; e < 4; e++) {
            unsigned mm = m[e];  // warp-uniform edge walk
            while (mm) {
                int src = __ffs(mm) - 1;
                mm &= mm - 1;
                int j = j0 + src * 4 + e;
                float s = __ldg(f1h + j) + f2i;
                s = s > 0.f ? s : NEG * s;
                float p = __expf(s - mhat);
                denom += p;
                uint4 r = __ldg((const uint4*)(supb + (size_t)j * 256));
                float2 x0 = __bfloat1622float2(*(__nv_bfloat162*)&r.x);
                float2 x1 = __bfloat1622float2(*(__nv_bfloat162*)&r.y);
                float2 x2 = __bfloat1622float2(*(__nv_bfloat162*)&r.z);
                float2 x3 = __bfloat1622float2(*(__nv_bfloat162*)&r.w);
                a0 += p * x0.x; a1 += p * x0.y; a2 += p * x1.x; a3 += p * x1.y;
                a4 += p * x2.x; a5 += p * x2.y; a6 += p * x3.x; a7 += p * x3.y;
            }
        }
    }

    float inv = 1.f / denom;  // self-loop guarantees denom > 0
    float* op = out + (size_t)i * 256 + lane * 8;
    float4 o0 = *(float4*)op;
    float4 o1 = *((float4*)op + 1);
    o0.x += a0 * inv; o0.y += a1 * inv; o0.z += a2 * inv; o0.w += a3 * inv;
    o1.x += a4 * inv; o1.y += a5 * inv; o1.z += a6 * inv; o1.w += a7 * inv;
    *(float4*)op = o0;
    *((float4*)op + 1) = o1;
}

// ------------------------------------------------------------------- launch
extern "C" void kernel_launch(void* const* d_in, const int* in_sizes, int n_in,
                              void* d_out, int out_size) {
    const float* inputs = (const float*)d_in[0];   // [8192, 256]
    const float* adj    = (const float*)d_in[1];   // [8192, 8192]
    const float* weight = (const float*)d_in[2];   // [256, 256]
    const float* wu     = (const float*)d_in[3];   // [4, 64, 1]
    const float* wv     = (const float*)d_in[4];   // [4, 64, 1]
    const float* bias   = (const float*)d_in[5];   // [1, 256]
    const float* projw  = (const float*)d_in[6];   // [256, 256]
    const float* projb  = (const float*)d_in[7];   // [256]
    float* out = (float*)d_out;                    // [8192, 256]

    prep_kernel<<<512, 256>>>(weight, projw, wu, wv);
    f1f2_kernel<<<128, 256>>>(inputs);
    gemm_kernel<<<dim3(8, 64), 256>>>(inputs, bias, projb, out);
    pv_kernel<<<1024, 256>>>(adj, out);
}

// round 4
// speedup vs baseline: 1.1420x; 1.0012x over previous
#include <cuda_runtime.h>
#include <cuda_bf16.h>
#include <cstdint>

// GraphAttnMultiHead: N=8192, IN_F=256, H=4, OUT_F=64 (H*OUT_F=256)
//
// Restructure:
//   f1[h,n] = X[n] @ u2[h]   where u2[h,k] = sum_o W[k,h*64+o]*wu[h,o]   (exact assoc. swap)
//   f2 likewise with wv. Computed straight from X -> independent of GEMM.
//   support stored ONLY as bf16 (PV gather traffic + GEMM stores halved);
//   fp32 accumulation everywhere.
//   softmax shift m_hat[h,i] = lrelu(gmax_f1[h] + f2[h,i]) (ratio-invariant upper bound).
//   out = (sum_j p*support[j])/(sum_j p) + bias + X@projW^T + proj_b
//
// Launch order: prep -> f1f2(+atomic gmax) -> gemm -> pv

#define NN 8192
#define NEG 0.2f

__device__ __nv_bfloat16 g_supb[NN * 256];   // 4 MB bf16 support
__device__ float g_bcat[256 * 512];          // [k][c]: c<256 -> W, c>=256 -> projW^T
__device__ float g_u2[4 * 256];              // [h][k]
__device__ float g_v2[4 * 256];
__device__ float g_f1[4 * NN];
__device__ float g_f2[4 * NN];
__device__ unsigned g_gmax_enc[4];

// monotone float<->uint order encoding
__device__ __forceinline__ unsigned enc_f(float f) {
    unsigned b = __float_as_uint(f);
    return (b & 0x80000000u) ? ~b : (b | 0x80000000u);
}
__device__ __forceinline__ float dec_f(unsigned e) {
    unsigned b = (e & 0x80000000u) ? (e ^ 0x80000000u) : ~e;
    return __uint_as_float(b);
}

// ------------------------------------------------------------------- prep
// Builds bcat, u2/v2, and inits gmax encodings.
__global__ void prep_kernel(const float* __restrict__ weight,
                            const float* __restrict__ projw,
                            const float* __restrict__ wu,
                            const float* __restrict__ wv) {
    int idx = blockIdx.x * blockDim.x + threadIdx.x;  // 131072
    int k = idx >> 9;
    int c = idx & 511;
    float v = (c < 256) ? weight[k * 256 + c] : projw[(c - 256) * 256 + k];
    g_bcat[k * 512 + c] = v;

    if (idx < 2048) {  // h(4) x k(256) x {u,v}(2)
        int which = idx & 1;
        int kk = (idx >> 1) & 255;
        int h = idx >> 9;
        const float* wrow = weight + kk * 256 + h * 64;
        const float* uv = (which ? wv : wu) + h * 64;
        float s = 0.f;
#pragma unroll 8
        for (int o = 0; o < 64; o++) s += wrow[o] * __ldg(uv + o);
        (which ? g_v2 : g_u2)[h * 256 + kk] = s;
    }
    if (idx < 4) g_gmax_enc[idx] = 0u;
}

// ------------------------------------------------- f1/f2 + fused global max
// Thread per (n,h). Warp-reduce per-h max (lanes stride-4), 4 atomics/warp.
__global__ void f1f2_kernel(const float* __restrict__ X) {
    int gid = blockIdx.x * blockDim.x + threadIdx.x;  // 32768
    int n = gid >> 2;
    int h = gid & 3;
    const float* xr = X + (size_t)n * 256;
    const float* u = g_u2 + h * 256;
    const float* v = g_v2 + h * 256;
    float s1 = 0.f, s2 = 0.f;
#pragma unroll 8
    for (int k = 0; k < 256; k++) {
        float x = __ldg(xr + k);
        s1 += x * u[k];
        s2 += x * v[k];
    }
    g_f1[h * NN + n] = s1;
    g_f2[h * NN + n] = s2;

    // per-h warp max (lanes with same h are stride-4 apart)
    float m = s1;
    m = fmaxf(m, __shfl_xor_sync(0xffffffffu, m, 4));
    m = fmaxf(m, __shfl_xor_sync(0xffffffffu, m, 8));
    m = fmaxf(m, __shfl_xor_sync(0xffffffffu, m, 16));
    if ((threadIdx.x & 31) < 4) atomicMax(&g_gmax_enc[h], enc_f(m));
}

// ------------------------------------------------- GEMM 8192 x 512 x 256 fp32
// C[:, 0:256] -> g_supb (bf16) ; C[:, 256:512] -> out fp32 (+ bias + proj_b)
__global__ __launch_bounds__(256) void gemm_kernel(
    const float* __restrict__ X, const float* __restrict__ bias,
    const float* __restrict__ projb, float* __restrict__ out) {
    __shared__ __align__(16) float As[16][132];
    __shared__ __align__(16) float Bs[16][68];

    int tid = threadIdx.x;
    int tx = tid & 15, ty = tid >> 4;
    int m0 = blockIdx.y * 128, n0 = blockIdx.x * 64;

    float acc[8][4];
#pragma unroll
    for (int ii = 0; ii < 8; ii++)
#pragma unroll
        for (int jj = 0; jj < 4; jj++) acc[ii][jj] = 0.f;

    int ar = tid >> 2, af = tid & 3;
    int bk = tid >> 4, bn = (tid & 15) * 4;

    for (int k0 = 0; k0 < 256; k0 += 16) {
#pragma unroll
        for (int r2 = 0; r2 < 2; r2++) {
            int row = ar + r2 * 64;
            float4 va = *(const float4*)(X + (size_t)(m0 + row) * 256 + k0 + af * 4);
            As[af * 4 + 0][row] = va.x;
            As[af * 4 + 1][row] = va.y;
            As[af * 4 + 2][row] = va.z;
            As[af * 4 + 3][row] = va.w;
        }
        float4 vb = *(const float4*)(g_bcat + (size_t)(k0 + bk) * 512 + n0 + bn);
        *(float4*)&Bs[bk][bn] = vb;
        __syncthreads();

#pragma unroll
        for (int k = 0; k < 16; k++) {
            float a[8], b[4];
            *(float4*)&a[0] = *(float4*)&As[k][ty * 8];
            *(float4*)&a[4] = *(float4*)&As[k][ty * 8 + 4];
            *(float4*)&b[0] = *(float4*)&Bs[k][tx * 4];
#pragma unroll
            for (int ii = 0; ii < 8; ii++)
#pragma unroll
                for (int jj = 0; jj < 4; jj++) acc[ii][jj] += a[ii] * b[jj];
        }
        __syncthreads();
    }

    if (n0 < 256) {
#pragma unroll
        for (int ii = 0; ii < 8; ii++) {
            int gm = m0 + ty * 8 + ii;
            __nv_bfloat162 b0 = __float22bfloat162_rn(make_float2(acc[ii][0], acc[ii][1]));
            __nv_bfloat162 b1 = __float22bfloat162_rn(make_float2(acc[ii][2], acc[ii][3]));
            uint2 st;
            st.x = *(unsigned*)&b0;
            st.y = *(unsigned*)&b1;
            *(uint2*)(g_supb + (size_t)gm * 256 + n0 + tx * 4) = st;
        }
    } else {
        int c2 = n0 - 256 + tx * 4;
        float4 bb = *(const float4*)(bias + c2);
        float4 pb = *(const float4*)(projb + c2);
#pragma unroll
        for (int ii = 0; ii < 8; ii++) {
            int gm = m0 + ty * 8 + ii;
            float4 v;
            v.x = acc[ii][0] + bb.x + pb.x;
            v.y = acc[ii][1] + bb.y + pb.y;
            v.z = acc[ii][2] + bb.z + pb.z;
            v.w = acc[ii][3] + bb.w + pb.w;
            *(float4*)(out + (size_t)gm * 256 + c2) = v;
        }
    }
}

// ------------------------------------------------- sparse PV (warp-per-row)
// Warp = row i; lane covers 8 channels (head = lane>>3). Ballot edge
// extraction; per edge one 16B bf16 gather per lane (512B/warp vs 1KB fp32).
__global__ __launch_bounds__(256) void pv_kernel(const float* __restrict__ adj,
                                                 float* __restrict__ out) {
    int warp = (blockIdx.x * 256 + threadIdx.x) >> 5;
    int lane = threadIdx.x & 31;
    int i = warp;
    int h = lane >> 3;

    float f2i = g_f2[h * NN + i];
    float t = dec_f(g_gmax_enc[h]) + f2i;
    float mhat = t > 0.f ? t : NEG * t;

    const float* __restrict__ arow = adj + (size_t)i * NN;
    const float* __restrict__ f1h = g_f1 + h * NN;
    const __nv_bfloat16* __restrict__ supb = g_supb + lane * 8;

    float a0 = 0.f, a1 = 0.f, a2 = 0.f, a3 = 0.f;
    float a4 = 0.f, a5 = 0.f, a6 = 0.f, a7 = 0.f;
    float denom = 0.f;

    for (int j0 = 0; j0 < NN; j0 += 128) {
        float4 v = *(const float4*)(arow + j0 + lane * 4);
        unsigned m[4];
        m[0] = __ballot_sync(0xffffffffu, v.x != 0.f);
        m[1] = __ballot_sync(0xffffffffu, v.y != 0.f);
        m[2] = __ballot_sync(0xffffffffu, v.z != 0.f);
        m[3] = __ballot_sync(0xffffffffu, v.w != 0.f);
#pragma unroll
        for (int e = 0; e < 4; e++) {
            unsigned mm = m[e];  // warp-uniform edge walk
            while (mm) {
                int src = __ffs(mm) - 1;
                mm &= mm - 1;
                int j = j0 + src * 4 + e;
                float s = __ldg(f1h + j) + f2i;
                s = s > 0.f ? s : NEG * s;
                float p = __expf(s - mhat);
                denom += p;
                uint4 r = __ldg((const uint4*)(supb + (size_t)j * 256));
                float2 x0 = __bfloat1622float2(*(__nv_bfloat162*)&r.x);
                float2 x1 = __bfloat1622float2(*(__nv_bfloat162*)&r.y);
                float2 x2 = __bfloat1622float2(*(__nv_bfloat162*)&r.z);
                float2 x3 = __bfloat1622float2(*(__nv_bfloat162*)&r.w);
                a0 += p * x0.x; a1 += p * x0.y; a2 += p * x1.x; a3 += p * x1.y;
                a4 += p * x2.x; a5 += p * x2.y; a6 += p * x3.x; a7 += p * x3.y;
            }
        }
    }

    float inv = 1.f / denom;  // self-loop guarantees denom > 0
    float* op = out + (size_t)i * 256 + lane * 8;
    float4 o0 = *(float4*)op;
    float4 o1 = *((float4*)op + 1);
    o0.x += a0 * inv; o0.y += a1 * inv; o0.z += a2 * inv; o0.w += a3 * inv;
    o1.x += a4 * inv; o1.y += a5 * inv; o1.z += a6 * inv; o1.w += a7 * inv;
    *(float4*)op = o0;
    *((float4*)op + 1) = o1;
}

// ------------------------------------------------------------------- launch
extern "C" void kernel_launch(void* const* d_in, const int* in_sizes, int n_in,
                              void* d_out, int out_size) {
    const float* inputs = (const float*)d_in[0];   // [8192, 256]
    const float* adj    = (const float*)d_in[1];   // [8192, 8192]
    const float* weight = (const float*)d_in[2];   // [256, 256]
    const float* wu     = (const float*)d_in[3];   // [4, 64, 1]
    const float* wv     = (const float*)d_in[4];   // [4, 64, 1]
    const float* bias   = (const float*)d_in[5];   // [1, 256]
    const float* projw  = (const float*)d_in[6];   // [256, 256]
    const float* projb  = (const float*)d_in[7];   // [256]
    float* out = (float*)d_out;                    // [8192, 256]

    prep_kernel<<<512, 256>>>(weight, projw, wu, wv);
    f1f2_kernel<<<128, 256>>>(inputs);
    gemm_kernel<<<dim3(8, 64), 256>>>(inputs, bias, projb, out);
    pv_kernel<<<1024, 256>>>(adj, out);
}